// round 2
// baseline (speedup 1.0000x reference)
#include <cuda_runtime.h>
#include <cuda_bf16.h>

// Scratch: concat buffer [N][256] : [f1(64) | f2(64) | f3(32) | f4(32) | f5(32) | f6(32)]
#define MAX_N 262144
__device__ float g_cat[(size_t)MAX_N * 256];

// ---------------------------------------------------------------------------
// blk1: y = relu(LN(x @ W + b))   (outC = 64)
// Block: 256 threads, 16 rows. thread: c = t&63, row-group rg = t>>6, 4 rows.
// ---------------------------------------------------------------------------
template <int INC>
__global__ __launch_bounds__(256)
void blk1_kernel(const float* __restrict__ x, int ldx,
                 const float* __restrict__ W,    // [INC][64]
                 const float* __restrict__ bias,
                 const float* __restrict__ gam,
                 const float* __restrict__ bet,
                 float* __restrict__ out, int ldo, int N)
{
    constexpr int TR = 16;
    constexpr int PX = INC + 4;            // pitch (keeps float4 alignment)
    extern __shared__ float sm[];
    float* WsT = sm;                       // [64][PX] transposed W
    float* Xs  = sm + 64 * PX;             // [TR][PX]
    __shared__ float red[8][4][2];         // [warp][local row][sum,sumsq]

    const int t  = threadIdx.x;
    const int c  = t & 63;
    const int rg = t >> 6;                 // 0..3
    const int base = blockIdx.x * TR;

    // Stage W transposed: WsT[c][j] = W[j][c]
    for (int idx = t; idx < INC * 64; idx += 256) {
        int j = idx >> 6, cc = idx & 63;
        WsT[cc * PX + j] = W[idx];
    }
    // Stage X rows
    for (int idx = t; idx < TR * INC; idx += 256) {
        int r = idx / INC, j = idx - r * INC;
        int row = base + r;
        Xs[r * PX + j] = (row < N) ? x[(size_t)row * ldx + j] : 0.f;
    }
    __syncthreads();

    float acc[4];
    const float bc = bias[c];
#pragma unroll
    for (int r = 0; r < 4; r++) acc[r] = bc;

    const int r0 = rg * 4;
#pragma unroll 8
    for (int j0 = 0; j0 < INC; j0 += 4) {
        float4 w = *(const float4*)&WsT[c * PX + j0];
#pragma unroll
        for (int r = 0; r < 4; r++) {
            float4 xv = *(const float4*)&Xs[(r0 + r) * PX + j0];
            acc[r] += xv.x * w.x + xv.y * w.y + xv.z * w.z + xv.w * w.w;
        }
    }

    // LayerNorm over 64 channels: each row is owned by a warp pair (2rg, 2rg+1)
    const int w = t >> 5;
    const int lane = t & 31;
#pragma unroll
    for (int r = 0; r < 4; r++) {
        float s = acc[r], s2 = acc[r] * acc[r];
#pragma unroll
        for (int o = 16; o > 0; o >>= 1) {
            s  += __shfl_xor_sync(0xffffffffu, s,  o);
            s2 += __shfl_xor_sync(0xffffffffu, s2, o);
        }
        if (lane == 0) { red[w][r][0] = s; red[w][r][1] = s2; }
    }
    __syncthreads();
    const int sib = w ^ 1;
    const float gc = gam[c], bec = bet[c];
#pragma unroll
    for (int r = 0; r < 4; r++) {
        float s  = red[w][r][0] + red[sib][r][0];
        float s2 = red[w][r][1] + red[sib][r][1];
        float mu  = s * (1.f / 64.f);
        float var = s2 * (1.f / 64.f) - mu * mu;
        float inv = rsqrtf(var + 1e-5f);
        float y = (acc[r] - mu) * inv * gc + bec;
        y = fmaxf(y, 0.f);
        int row = base + r0 + r;
        if (row < N) out[(size_t)row * ldo + c] = y;
    }
}

// ---------------------------------------------------------------------------
// conv: y = relu(LN(b + sum_k gather_k(x) @ W[k]))   (outC = 32)
// Block: 256 threads, 64 rows. thread: c = t&31, row-group rg = t>>5, 8 rows.
// ---------------------------------------------------------------------------
template <int INC>
__global__ __launch_bounds__(256)
void conv_kernel(const float* __restrict__ x, int ldx,
                 const int* __restrict__ nbr,        // [N][27]
                 const float* __restrict__ W,        // [27][INC][32]
                 const float* __restrict__ bias,
                 const float* __restrict__ gam,
                 const float* __restrict__ bet,
                 float* __restrict__ out, int ldo, int N)
{
    constexpr int TR = 64;
    constexpr int PX = INC + 4;
    __shared__ float Xs[TR][PX];       // gathered rows, natural layout
    __shared__ float WsT[32][PX];      // W[k] transposed: WsT[c][j]
    __shared__ int   nb[TR];

    const int t  = threadIdx.x;
    const int c  = t & 31;
    const int rg = t >> 5;             // 0..7
    const int base = blockIdx.x * TR;

    float acc[8];
    const float bc = bias[c];
#pragma unroll
    for (int r = 0; r < 8; r++) acc[r] = bc;

    const int grow = t >> 2;           // gather: 4 threads per row
    const int q    = t & 3;
    const int r0   = rg * 8;

    for (int k = 0; k < 27; k++) {
        // Stage W[k] transposed
        const float* Wk = W + k * INC * 32;
        for (int idx = t; idx < INC * 32; idx += 256) {
            int j = idx >> 5, cc = idx & 31;
            WsT[cc][j] = Wk[idx];
        }
        if (t < TR) {
            int row = base + t;
            nb[t] = (row < N) ? nbr[row * 27 + k] : -1;
        }
        __syncthreads();

        // Gather 64 neighbor rows (zero for invalid)
        {
            int ni = nb[grow];
#pragma unroll
            for (int u = 0; u < INC / 16; u++) {
                int j4 = q + u * 4;                    // float4 index
                float4 v = make_float4(0.f, 0.f, 0.f, 0.f);
                if (ni >= 0)
                    v = __ldg((const float4*)(x + (size_t)ni * ldx) + j4);
                *(float4*)&Xs[grow][j4 * 4] = v;
            }
        }
        __syncthreads();

        // Register-blocked accumulate: 8 rows x 1 channel per thread
#pragma unroll
        for (int j0 = 0; j0 < INC; j0 += 4) {
            float4 w = *(const float4*)&WsT[c][j0];
#pragma unroll
            for (int r = 0; r < 8; r++) {
                float4 xv = *(const float4*)&Xs[r0 + r][j0];
                acc[r] += xv.x * w.x + xv.y * w.y + xv.z * w.z + xv.w * w.w;
            }
        }
        __syncthreads();
    }

    // LayerNorm over 32 channels (one warp owns each row fully) + ReLU
    const float gc = gam[c], bec = bet[c];
#pragma unroll
    for (int r = 0; r < 8; r++) {
        float v = acc[r];
        float s = v, s2 = v * v;
#pragma unroll
        for (int o = 16; o > 0; o >>= 1) {
            s  += __shfl_xor_sync(0xffffffffu, s,  o);
            s2 += __shfl_xor_sync(0xffffffffu, s2, o);
        }
        float mu  = s * (1.f / 32.f);
        float var = s2 * (1.f / 32.f) - mu * mu;
        float inv = rsqrtf(var + 1e-5f);
        float y = (v - mu) * inv * gc + bec;
        y = fmaxf(y, 0.f);
        int row = base + r0 + r;
        if (row < N) out[(size_t)row * ldo + c] = y;
    }
}

// ---------------------------------------------------------------------------
extern "C" void kernel_launch(void* const* d_in, const int* in_sizes, int n_in,
                              void* d_out, int out_size)
{
    const float* vox = (const float*)d_in[0];
    const int*   nbr = (const int*)d_in[1];
    const float* W1  = (const float*)d_in[2];
    const float* b1  = (const float*)d_in[3];
    const float* g1  = (const float*)d_in[4];
    const float* be1 = (const float*)d_in[5];
    const float* W2  = (const float*)d_in[6];
    const float* b2  = (const float*)d_in[7];
    const float* g2  = (const float*)d_in[8];
    const float* be2 = (const float*)d_in[9];
    const float* W3  = (const float*)d_in[10];
    const float* b3  = (const float*)d_in[11];
    const float* g3  = (const float*)d_in[12];
    const float* be3 = (const float*)d_in[13];
    const float* W4  = (const float*)d_in[14];
    const float* b4  = (const float*)d_in[15];
    const float* g4  = (const float*)d_in[16];
    const float* be4 = (const float*)d_in[17];
    const float* W5  = (const float*)d_in[18];
    const float* b5  = (const float*)d_in[19];
    const float* g5  = (const float*)d_in[20];
    const float* be5 = (const float*)d_in[21];
    const float* W6  = (const float*)d_in[22];
    const float* b6  = (const float*)d_in[23];
    const float* g6  = (const float*)d_in[24];
    const float* be6 = (const float*)d_in[25];
    const float* W7  = (const float*)d_in[26];
    const float* b7  = (const float*)d_in[27];
    const float* g7  = (const float*)d_in[28];
    const float* be7 = (const float*)d_in[29];

    const int N = in_sizes[0] / 64;

    float* cat = nullptr;
    cudaGetSymbolAddress((void**)&cat, g_cat);

    const int nb1 = (N + 15) / 16;
    const int nbc = (N + 63) / 64;

    const int smem64  = (64 + 16) * (64 + 4)  * 4;   // 21,760 B
    const int smem256 = (64 + 16) * (256 + 4) * 4;   // 83,200 B
    cudaFuncSetAttribute(blk1_kernel<64>,
                         cudaFuncAttributeMaxDynamicSharedMemorySize, smem64);
    cudaFuncSetAttribute(blk1_kernel<256>,
                         cudaFuncAttributeMaxDynamicSharedMemorySize, smem256);

    // f1, f2
    blk1_kernel<64><<<nb1, 256, smem64>>>(vox, 64, W1, b1, g1, be1, cat + 0,  256, N);
    blk1_kernel<64><<<nb1, 256, smem64>>>(vox, 64, W2, b2, g2, be2, cat + 64, 256, N);
    // f3..f6 (submanifold convs, chained)
    conv_kernel<64><<<nbc, 256>>>(cat + 64,  256, nbr, W3, b3, g3, be3, cat + 128, 256, N);
    conv_kernel<32><<<nbc, 256>>>(cat + 128, 256, nbr, W4, b4, g4, be4, cat + 160, 256, N);
    conv_kernel<32><<<nbc, 256>>>(cat + 160, 256, nbr, W5, b5, g5, be5, cat + 192, 256, N);
    conv_kernel<32><<<nbc, 256>>>(cat + 192, 256, nbr, W6, b6, g6, be6, cat + 224, 256, N);
    // final: blk1 over concat(256) -> out(64)
    blk1_kernel<256><<<nb1, 256, smem256>>>(cat, 256, W7, b7, g7, be7,
                                            (float*)d_out, 64, N);
}

// round 3
// speedup vs baseline: 2.0379x; 2.0379x over previous
#include <cuda_runtime.h>

#define MAX_N 262144
__device__ float g_cat[(size_t)MAX_N * 256];
__device__ __align__(16) float g_zero[256];   // zero-initialized device global

typedef unsigned long long u64;

__device__ __forceinline__ u64 pk2(float a, float b) {
    u64 r;
    asm("mov.b64 %0, {%1, %2};" : "=l"(r)
        : "r"(__float_as_uint(a)), "r"(__float_as_uint(b)));
    return r;
}
__device__ __forceinline__ u64 dup2(float a) {
    u64 r; unsigned ai = __float_as_uint(a);
    asm("mov.b64 %0, {%1, %1};" : "=l"(r) : "r"(ai));
    return r;
}
__device__ __forceinline__ float2 up2(u64 v) {
    unsigned a, b;
    asm("mov.b64 {%0, %1}, %2;" : "=r"(a), "=r"(b) : "l"(v));
    return make_float2(__uint_as_float(a), __uint_as_float(b));
}
__device__ __forceinline__ void fma2(u64& d, u64 a, u64 b) {
    asm("fma.rn.f32x2 %0, %1, %2, %0;" : "+l"(d) : "l"(a), "l"(b));
}
__device__ __forceinline__ u64 d2u(double d) { return __double_as_longlong(d); }

// ---------------------------------------------------------------------------
// blk1: y = relu(LN(x @ W + b)), outC = 64.
// 256 threads, 128 rows/block. Thread tile: 4 rows x 8 channels (f32x2 pairs).
// K processed in chunks of 64 staged in smem. W staged quad-permuted so the
// per-warp 8 distinct float4 fetches hit 8 distinct bank-quads (1 wavefront).
// ---------------------------------------------------------------------------
template <int INC>
__global__ __launch_bounds__(256)
void blk1_kernel(const float* __restrict__ x, int ldx,
                 const float* __restrict__ W,      // [INC][64]
                 const float* __restrict__ bias,
                 const float* __restrict__ gam,
                 const float* __restrict__ bet,
                 float* __restrict__ out, int ldo, int N)
{
    constexpr int KC = 64;
    constexpr int PX = 68;
    constexpr int PW = 68;
    constexpr int ROWS = 128;
    extern __shared__ float sm[];
    float* Xs = sm;                 // [ROWS][PX], XOR-swizzled float4 slots
    float* Ws = sm + ROWS * PX;     // [KC][PW], quad-permuted

    const int t   = threadIdx.x;
    const int cg  = t & 7;          // 8 channel groups x 8 ch
    const int rg  = t >> 3;         // 0..31, 4 rows each
    const int r0  = rg * 4;
    const int c0  = cg * 8;
    const int key = rg & 7;
    const int base = blockIdx.x * ROWS;

    u64 acc[4][4];
    {
        u64 b0 = pk2(bias[c0 + 0], bias[c0 + 1]);
        u64 b1 = pk2(bias[c0 + 2], bias[c0 + 3]);
        u64 b2 = pk2(bias[c0 + 4], bias[c0 + 5]);
        u64 b3 = pk2(bias[c0 + 6], bias[c0 + 7]);
#pragma unroll
        for (int rr = 0; rr < 4; rr++) {
            acc[rr][0] = b0; acc[rr][1] = b1; acc[rr][2] = b2; acc[rr][3] = b3;
        }
    }

    for (int k0 = 0; k0 < INC; k0 += KC) {
        __syncthreads();
        // Stage W chunk: logical quad q (channels 4q..4q+3) -> phys quad (q>>1)+8*(q&1)
        for (int idx = t; idx < KC * 16; idx += 256) {
            int j = idx >> 4, q = idx & 15;
            int pq = (q >> 1) + ((q & 1) << 3);
            *(float4*)&Ws[j * PW + pq * 4] =
                *(const float4*)&W[(size_t)(k0 + j) * 64 + q * 4];
        }
        // Stage X chunk with XOR swizzle on float4 slot
        for (int idx = t; idx < ROWS * 16; idx += 256) {
            int r = idx >> 4, u = idx & 15;
            int row = base + r;
            float4 v = make_float4(0.f, 0.f, 0.f, 0.f);
            if (row < N)
                v = *(const float4*)&x[(size_t)row * ldx + k0 + u * 4];
            *(float4*)&Xs[r * PX + ((u ^ ((r >> 2) & 7)) << 2)] = v;
        }
        __syncthreads();

#pragma unroll
        for (int j0 = 0; j0 < KC; j0 += 4) {
            const int slot = ((j0 >> 2) ^ key) << 2;
            float4 xv[4];
#pragma unroll
            for (int rr = 0; rr < 4; rr++)
                xv[rr] = *(const float4*)&Xs[(r0 + rr) * PX + slot];
#pragma unroll
            for (int jj = 0; jj < 4; jj++) {
                double2 wa = *(const double2*)&Ws[(j0 + jj) * PW + (cg << 2)];
                double2 wb = *(const double2*)&Ws[(j0 + jj) * PW + 32 + (cg << 2)];
                u64 w0 = d2u(wa.x), w1 = d2u(wa.y);
                u64 w2_ = d2u(wb.x), w3 = d2u(wb.y);
#pragma unroll
                for (int rr = 0; rr < 4; rr++) {
                    float xs_ = (jj == 0) ? xv[rr].x : (jj == 1) ? xv[rr].y
                              : (jj == 2) ? xv[rr].z : xv[rr].w;
                    u64 xd = dup2(xs_);
                    fma2(acc[rr][0], xd, w0);
                    fma2(acc[rr][1], xd, w1);
                    fma2(acc[rr][2], xd, w2_);
                    fma2(acc[rr][3], xd, w3);
                }
            }
        }
    }

    // LayerNorm(64) + ReLU. Row's 64 channels live in 8 adjacent lanes.
    float4 g0 = *(const float4*)&gam[c0], g1 = *(const float4*)&gam[c0 + 4];
    float4 e0 = *(const float4*)&bet[c0], e1 = *(const float4*)&bet[c0 + 4];
#pragma unroll
    for (int rr = 0; rr < 4; rr++) {
        float2 v0 = up2(acc[rr][0]), v1 = up2(acc[rr][1]);
        float2 v2 = up2(acc[rr][2]), v3 = up2(acc[rr][3]);
        float s  = v0.x + v0.y + v1.x + v1.y + v2.x + v2.y + v3.x + v3.y;
        float s2 = v0.x*v0.x + v0.y*v0.y + v1.x*v1.x + v1.y*v1.y
                 + v2.x*v2.x + v2.y*v2.y + v3.x*v3.x + v3.y*v3.y;
#pragma unroll
        for (int o = 4; o > 0; o >>= 1) {
            s  += __shfl_xor_sync(0xffffffffu, s,  o);
            s2 += __shfl_xor_sync(0xffffffffu, s2, o);
        }
        float mu  = s * (1.f / 64.f);
        float var = s2 * (1.f / 64.f) - mu * mu;
        float inv = rsqrtf(var + 1e-5f);
        int row = base + r0 + rr;
        if (row < N) {
            float4 o0, o1;
            o0.x = fmaxf((v0.x - mu) * inv * g0.x + e0.x, 0.f);
            o0.y = fmaxf((v0.y - mu) * inv * g0.y + e0.y, 0.f);
            o0.z = fmaxf((v1.x - mu) * inv * g0.z + e0.z, 0.f);
            o0.w = fmaxf((v1.y - mu) * inv * g0.w + e0.w, 0.f);
            o1.x = fmaxf((v2.x - mu) * inv * g1.x + e1.x, 0.f);
            o1.y = fmaxf((v2.y - mu) * inv * g1.y + e1.y, 0.f);
            o1.z = fmaxf((v3.x - mu) * inv * g1.z + e1.z, 0.f);
            o1.w = fmaxf((v3.y - mu) * inv * g1.w + e1.w, 0.f);
            *(float4*)&out[(size_t)row * ldo + c0]     = o0;
            *(float4*)&out[(size_t)row * ldo + c0 + 4] = o1;
        }
    }
}

// ---------------------------------------------------------------------------
// conv: y = relu(LN(b + sum_k gather_k(x) @ W[k])), outC = 32.
// 256 threads, 256 rows/block. Thread tile: 4 rows x 8 channels.
// Per warp: only 4 distinct W float4 addresses (8-way broadcast, 1 wavefront),
// 8 distinct swizzled X addresses (1 wavefront).
// ---------------------------------------------------------------------------
template <int INC>
__global__ __launch_bounds__(256)
void conv_kernel(const float* __restrict__ x, int ldx,
                 const int* __restrict__ nbr,      // [N][27]
                 const float* __restrict__ W,      // [27][INC][32]
                 const float* __restrict__ bias,
                 const float* __restrict__ gam,
                 const float* __restrict__ bet,
                 float* __restrict__ out, int ldo, int N)
{
    constexpr int PX = INC + 4;
    constexpr int PW = 36;
    constexpr int ROWS = 256;
    constexpr int U = INC / 4;
    extern __shared__ float sm[];
    float* Xs = sm;                 // [ROWS][PX]
    float* Ws = sm + ROWS * PX;     // [INC][PW] natural [j][c]

    const int t   = threadIdx.x;
    const int cg  = t & 3;          // 4 channel groups x 8 ch
    const int rg  = t >> 2;         // 0..63, 4 rows each
    const int r0  = rg * 4;
    const int c0  = cg * 8;
    const int key = rg & 7;
    const int base  = blockIdx.x * ROWS;
    const int myrow = base + t;
    const int skey  = (t >> 2) & 7;

    u64 acc[4][4];
    {
        u64 b0 = pk2(bias[c0 + 0], bias[c0 + 1]);
        u64 b1 = pk2(bias[c0 + 2], bias[c0 + 3]);
        u64 b2 = pk2(bias[c0 + 4], bias[c0 + 5]);
        u64 b3 = pk2(bias[c0 + 6], bias[c0 + 7]);
#pragma unroll
        for (int rr = 0; rr < 4; rr++) {
            acc[rr][0] = b0; acc[rr][1] = b1; acc[rr][2] = b2; acc[rr][3] = b3;
        }
    }

    for (int k = 0; k < 27; k++) {
        __syncthreads();
        const float* Wk = W + (size_t)k * INC * 32;
        for (int idx = t; idx < INC * 8; idx += 256) {
            int j = idx >> 3, q = idx & 7;
            *(float4*)&Ws[j * PW + q * 4] = *(const float4*)&Wk[j * 32 + q * 4];
        }
        {   // each thread gathers one row; invalid neighbor -> zero row
            int ni = (myrow < N) ? nbr[(size_t)myrow * 27 + k] : -1;
            const float* src = (ni >= 0) ? (x + (size_t)ni * ldx) : g_zero;
#pragma unroll
            for (int u = 0; u < U; u++) {
                float4 v = __ldg((const float4*)src + u);
                *(float4*)&Xs[t * PX + ((u ^ skey) << 2)] = v;
            }
        }
        __syncthreads();

#pragma unroll
        for (int j0 = 0; j0 < INC; j0 += 4) {
            const int slot = ((j0 >> 2) ^ key) << 2;
            float4 xv[4];
#pragma unroll
            for (int rr = 0; rr < 4; rr++)
                xv[rr] = *(const float4*)&Xs[(r0 + rr) * PX + slot];
#pragma unroll
            for (int jj = 0; jj < 4; jj++) {
                double2 wa = *(const double2*)&Ws[(j0 + jj) * PW + c0];
                double2 wb = *(const double2*)&Ws[(j0 + jj) * PW + c0 + 4];
                u64 w0 = d2u(wa.x), w1 = d2u(wa.y);
                u64 w2_ = d2u(wb.x), w3 = d2u(wb.y);
#pragma unroll
                for (int rr = 0; rr < 4; rr++) {
                    float xs_ = (jj == 0) ? xv[rr].x : (jj == 1) ? xv[rr].y
                              : (jj == 2) ? xv[rr].z : xv[rr].w;
                    u64 xd = dup2(xs_);
                    fma2(acc[rr][0], xd, w0);
                    fma2(acc[rr][1], xd, w1);
                    fma2(acc[rr][2], xd, w2_);
                    fma2(acc[rr][3], xd, w3);
                }
            }
        }
    }

    // LayerNorm(32) + ReLU. Row's 32 channels live in 4 adjacent lanes.
    float4 g0 = *(const float4*)&gam[c0], g1 = *(const float4*)&gam[c0 + 4];
    float4 e0 = *(const float4*)&bet[c0], e1 = *(const float4*)&bet[c0 + 4];
#pragma unroll
    for (int rr = 0; rr < 4; rr++) {
        float2 v0 = up2(acc[rr][0]), v1 = up2(acc[rr][1]);
        float2 v2 = up2(acc[rr][2]), v3 = up2(acc[rr][3]);
        float s  = v0.x + v0.y + v1.x + v1.y + v2.x + v2.y + v3.x + v3.y;
        float s2 = v0.x*v0.x + v0.y*v0.y + v1.x*v1.x + v1.y*v1.y
                 + v2.x*v2.x + v2.y*v2.y + v3.x*v3.x + v3.y*v3.y;
#pragma unroll
        for (int o = 2; o > 0; o >>= 1) {
            s  += __shfl_xor_sync(0xffffffffu, s,  o);
            s2 += __shfl_xor_sync(0xffffffffu, s2, o);
        }
        float mu  = s * (1.f / 32.f);
        float var = s2 * (1.f / 32.f) - mu * mu;
        float inv = rsqrtf(var + 1e-5f);
        int row = base + r0 + rr;
        if (row < N) {
            float4 o0, o1;
            o0.x = fmaxf((v0.x - mu) * inv * g0.x + e0.x, 0.f);
            o0.y = fmaxf((v0.y - mu) * inv * g0.y + e0.y, 0.f);
            o0.z = fmaxf((v1.x - mu) * inv * g0.z + e0.z, 0.f);
            o0.w = fmaxf((v1.y - mu) * inv * g0.w + e0.w, 0.f);
            o1.x = fmaxf((v2.x - mu) * inv * g1.x + e1.x, 0.f);
            o1.y = fmaxf((v2.y - mu) * inv * g1.y + e1.y, 0.f);
            o1.z = fmaxf((v3.x - mu) * inv * g1.z + e1.z, 0.f);
            o1.w = fmaxf((v3.y - mu) * inv * g1.w + e1.w, 0.f);
            *(float4*)&out[(size_t)row * ldo + c0]     = o0;
            *(float4*)&out[(size_t)row * ldo + c0 + 4] = o1;
        }
    }
}

// ---------------------------------------------------------------------------
extern "C" void kernel_launch(void* const* d_in, const int* in_sizes, int n_in,
                              void* d_out, int out_size)
{
    const float* vox = (const float*)d_in[0];
    const int*   nbr = (const int*)d_in[1];
    const float* W1  = (const float*)d_in[2];
    const float* b1  = (const float*)d_in[3];
    const float* g1  = (const float*)d_in[4];
    const float* be1 = (const float*)d_in[5];
    const float* W2  = (const float*)d_in[6];
    const float* b2  = (const float*)d_in[7];
    const float* g2  = (const float*)d_in[8];
    const float* be2 = (const float*)d_in[9];
    const float* W3  = (const float*)d_in[10];
    const float* b3  = (const float*)d_in[11];
    const float* g3  = (const float*)d_in[12];
    const float* be3 = (const float*)d_in[13];
    const float* W4  = (const float*)d_in[14];
    const float* b4  = (const float*)d_in[15];
    const float* g4  = (const float*)d_in[16];
    const float* be4 = (const float*)d_in[17];
    const float* W5  = (const float*)d_in[18];
    const float* b5  = (const float*)d_in[19];
    const float* g5  = (const float*)d_in[20];
    const float* be5 = (const float*)d_in[21];
    const float* W6  = (const float*)d_in[22];
    const float* b6  = (const float*)d_in[23];
    const float* g6  = (const float*)d_in[24];
    const float* be6 = (const float*)d_in[25];
    const float* W7  = (const float*)d_in[26];
    const float* b7  = (const float*)d_in[27];
    const float* g7  = (const float*)d_in[28];
    const float* be7 = (const float*)d_in[29];

    const int N = in_sizes[0] / 64;

    float* cat = nullptr;
    cudaGetSymbolAddress((void**)&cat, g_cat);

    const int nb1 = (N + 127) / 128;
    const int nbc = (N + 255) / 256;

    const int smem_blk1 = (128 * 68 + 64 * 68) * 4;   // 52,224 B
    const int smem_c64  = (256 * 68 + 64 * 36) * 4;   // 78,848 B
    const int smem_c32  = (256 * 36 + 32 * 36) * 4;   // 41,472 B
    cudaFuncSetAttribute(blk1_kernel<64>,
                         cudaFuncAttributeMaxDynamicSharedMemorySize, smem_blk1);
    cudaFuncSetAttribute(blk1_kernel<256>,
                         cudaFuncAttributeMaxDynamicSharedMemorySize, smem_blk1);
    cudaFuncSetAttribute(conv_kernel<64>,
                         cudaFuncAttributeMaxDynamicSharedMemorySize, smem_c64);
    cudaFuncSetAttribute(conv_kernel<32>,
                         cudaFuncAttributeMaxDynamicSharedMemorySize, smem_c32);

    // f1, f2
    blk1_kernel<64><<<nb1, 256, smem_blk1>>>(vox, 64, W1, b1, g1, be1, cat + 0,  256, N);
    blk1_kernel<64><<<nb1, 256, smem_blk1>>>(vox, 64, W2, b2, g2, be2, cat + 64, 256, N);
    // f3..f6 (submanifold convs, chained)
    conv_kernel<64><<<nbc, 256, smem_c64>>>(cat + 64,  256, nbr, W3, b3, g3, be3, cat + 128, 256, N);
    conv_kernel<32><<<nbc, 256, smem_c32>>>(cat + 128, 256, nbr, W4, b4, g4, be4, cat + 160, 256, N);
    conv_kernel<32><<<nbc, 256, smem_c32>>>(cat + 160, 256, nbr, W5, b5, g5, be5, cat + 192, 256, N);
    conv_kernel<32><<<nbc, 256, smem_c32>>>(cat + 192, 256, nbr, W6, b6, g6, be6, cat + 224, 256, N);
    // final: blk1 over concat(256) -> out(64)
    blk1_kernel<256><<<nb1, 256, smem_blk1>>>(cat, 256, W7, b7, g7, be7,
                                              (float*)d_out, 64, N);
}

// round 5
// speedup vs baseline: 4.1776x; 2.0500x over previous
#include <cuda_runtime.h>

#define MAX_N 262144
__device__ float g_cat[(size_t)MAX_N * 256];

typedef unsigned long long u64;

__device__ __forceinline__ u64 pk2(float a, float b) {
    u64 r;
    asm("mov.b64 %0, {%1, %2};" : "=l"(r)
        : "r"(__float_as_uint(a)), "r"(__float_as_uint(b)));
    return r;
}
__device__ __forceinline__ u64 dup2(float a) {
    u64 r; unsigned ai = __float_as_uint(a);
    asm("mov.b64 %0, {%1, %1};" : "=l"(r) : "r"(ai));
    return r;
}
__device__ __forceinline__ float2 up2(u64 v) {
    unsigned a, b;
    asm("mov.b64 {%0, %1}, %2;" : "=r"(a), "=r"(b) : "l"(v));
    return make_float2(__uint_as_float(a), __uint_as_float(b));
}
__device__ __forceinline__ void fma2(u64& d, u64 a, u64 b) {
    asm("fma.rn.f32x2 %0, %1, %2, %0;" : "+l"(d) : "l"(a), "l"(b));
}
__device__ __forceinline__ u64 addp(u64 a, u64 b) {
    u64 r;
    asm("add.rn.f32x2 %0, %1, %2;" : "=l"(r) : "l"(a), "l"(b));
    return r;
}
__device__ __forceinline__ u64 d2u(double d) { return __double_as_longlong(d); }

// ---------------------------------------------------------------------------
// blk1: y = relu(LN(x @ W + b)), outC = 64.  (unchanged from R2)
// ---------------------------------------------------------------------------
template <int INC>
__global__ __launch_bounds__(256)
void blk1_kernel(const float* __restrict__ x, int ldx,
                 const float* __restrict__ W,      // [INC][64]
                 const float* __restrict__ bias,
                 const float* __restrict__ gam,
                 const float* __restrict__ bet,
                 float* __restrict__ out, int ldo, int N)
{
    constexpr int KC = 64;
    constexpr int PX = 68;
    constexpr int PW = 68;
    constexpr int ROWS = 128;
    extern __shared__ float sm[];
    float* Xs = sm;                 // [ROWS][PX]
    float* Ws = sm + ROWS * PX;     // [KC][PW], quad-permuted

    const int t   = threadIdx.x;
    const int cg  = t & 7;
    const int rg  = t >> 3;
    const int r0  = rg * 4;
    const int c0  = cg * 8;
    const int key = rg & 7;
    const int base = blockIdx.x * ROWS;

    u64 acc[4][4];
    {
        u64 b0 = pk2(bias[c0 + 0], bias[c0 + 1]);
        u64 b1 = pk2(bias[c0 + 2], bias[c0 + 3]);
        u64 b2 = pk2(bias[c0 + 4], bias[c0 + 5]);
        u64 b3 = pk2(bias[c0 + 6], bias[c0 + 7]);
#pragma unroll
        for (int rr = 0; rr < 4; rr++) {
            acc[rr][0] = b0; acc[rr][1] = b1; acc[rr][2] = b2; acc[rr][3] = b3;
        }
    }

    for (int k0 = 0; k0 < INC; k0 += KC) {
        __syncthreads();
        for (int idx = t; idx < KC * 16; idx += 256) {
            int j = idx >> 4, q = idx & 15;
            int pq = (q >> 1) + ((q & 1) << 3);
            *(float4*)&Ws[j * PW + pq * 4] =
                *(const float4*)&W[(size_t)(k0 + j) * 64 + q * 4];
        }
        for (int idx = t; idx < ROWS * 16; idx += 256) {
            int r = idx >> 4, u = idx & 15;
            int row = base + r;
            float4 v = make_float4(0.f, 0.f, 0.f, 0.f);
            if (row < N)
                v = *(const float4*)&x[(size_t)row * ldx + k0 + u * 4];
            *(float4*)&Xs[r * PX + ((u ^ ((r >> 2) & 7)) << 2)] = v;
        }
        __syncthreads();

#pragma unroll
        for (int j0 = 0; j0 < KC; j0 += 4) {
            const int slot = ((j0 >> 2) ^ key) << 2;
            float4 xv[4];
#pragma unroll
            for (int rr = 0; rr < 4; rr++)
                xv[rr] = *(const float4*)&Xs[(r0 + rr) * PX + slot];
#pragma unroll
            for (int jj = 0; jj < 4; jj++) {
                double2 wa = *(const double2*)&Ws[(j0 + jj) * PW + (cg << 2)];
                double2 wb = *(const double2*)&Ws[(j0 + jj) * PW + 32 + (cg << 2)];
                u64 w0 = d2u(wa.x), w1 = d2u(wa.y);
                u64 w2_ = d2u(wb.x), w3 = d2u(wb.y);
#pragma unroll
                for (int rr = 0; rr < 4; rr++) {
                    float xs_ = (jj == 0) ? xv[rr].x : (jj == 1) ? xv[rr].y
                              : (jj == 2) ? xv[rr].z : xv[rr].w;
                    u64 xd = dup2(xs_);
                    fma2(acc[rr][0], xd, w0);
                    fma2(acc[rr][1], xd, w1);
                    fma2(acc[rr][2], xd, w2_);
                    fma2(acc[rr][3], xd, w3);
                }
            }
        }
    }

    float4 g0 = *(const float4*)&gam[c0], g1 = *(const float4*)&gam[c0 + 4];
    float4 e0 = *(const float4*)&bet[c0], e1 = *(const float4*)&bet[c0 + 4];
#pragma unroll
    for (int rr = 0; rr < 4; rr++) {
        float2 v0 = up2(acc[rr][0]), v1 = up2(acc[rr][1]);
        float2 v2 = up2(acc[rr][2]), v3 = up2(acc[rr][3]);
        float s  = v0.x + v0.y + v1.x + v1.y + v2.x + v2.y + v3.x + v3.y;
        float s2 = v0.x*v0.x + v0.y*v0.y + v1.x*v1.x + v1.y*v1.y
                 + v2.x*v2.x + v2.y*v2.y + v3.x*v3.x + v3.y*v3.y;
#pragma unroll
        for (int o = 4; o > 0; o >>= 1) {
            s  += __shfl_xor_sync(0xffffffffu, s,  o);
            s2 += __shfl_xor_sync(0xffffffffu, s2, o);
        }
        float mu  = s * (1.f / 64.f);
        float var = s2 * (1.f / 64.f) - mu * mu;
        float inv = rsqrtf(var + 1e-5f);
        int row = base + r0 + rr;
        if (row < N) {
            float4 o0, o1;
            o0.x = fmaxf((v0.x - mu) * inv * g0.x + e0.x, 0.f);
            o0.y = fmaxf((v0.y - mu) * inv * g0.y + e0.y, 0.f);
            o0.z = fmaxf((v1.x - mu) * inv * g0.z + e0.z, 0.f);
            o0.w = fmaxf((v1.y - mu) * inv * g0.w + e0.w, 0.f);
            o1.x = fmaxf((v2.x - mu) * inv * g1.x + e1.x, 0.f);
            o1.y = fmaxf((v2.y - mu) * inv * g1.y + e1.y, 0.f);
            o1.z = fmaxf((v3.x - mu) * inv * g1.z + e1.z, 0.f);
            o1.w = fmaxf((v3.y - mu) * inv * g1.w + e1.w, 0.f);
            *(float4*)&out[(size_t)row * ldo + c0]     = o0;
            *(float4*)&out[(size_t)row * ldo + c0 + 4] = o1;
        }
    }
}

// ---------------------------------------------------------------------------
// Sparse submanifold conv: y = relu(LN(b + sum_valid_k gather_k(x) @ W[k]))
// k=13 is the (always-valid) self tap -> dense register-tiled GEMM.
// Other k: ~3.2% valid -> ballot-compacted entry list, warp-per-entry,
// accumulated into a smem tile initialized with bias.
// ---------------------------------------------------------------------------
template <int INC>
__global__ __launch_bounds__(256)
void conv_kernel(const float* __restrict__ x, int ldx,
                 const int* __restrict__ nbr,      // [N][27]
                 const float* __restrict__ W,      // [27][INC][32]
                 const float* __restrict__ bias,
                 const float* __restrict__ gam,
                 const float* __restrict__ bet,
                 float* __restrict__ out, int ldo, int N)
{
    constexpr int ROWS = 256;
    constexpr int ACP  = 34;      // accum row pitch (floats), 8B-aligned pairs
    constexpr int U    = INC / 4;
    extern __shared__ float sm[];
    float* accum = sm;                       // [256][ACP]
    float* Ws    = sm + 256 * ACP;           // [INC][32]
    float* Xs    = Ws + INC * 32;            // [256][INC], swizzled
    int*   ent_r = (int*)(Xs + 256 * INC);   // [256]
    int*   ent_n = ent_r + 256;              // [256]
    __shared__ int nV;

    const int t     = threadIdx.x;
    const int lane  = t & 31;
    const int wid   = t >> 5;
    const int base  = blockIdx.x * ROWS;
    const int myrow = base + t;

    // init accum row t with bias
    {
        float* ar = accum + t * ACP;
#pragma unroll
        for (int c = 0; c < 32; c++) ar[c] = __ldg(&bias[c]);
    }
    // stage own row into Xs (swizzled), used by the dense self phase
    {
        const int skey = (t >> 2) & 7;
        const float4* xr = (const float4*)(x + (size_t)myrow * ldx);
#pragma unroll
        for (int u = 0; u < U; u++) {
            float4 v = make_float4(0.f, 0.f, 0.f, 0.f);
            if (myrow < N) v = __ldg(xr + u);
            *(float4*)&Xs[t * INC + ((u ^ skey) << 2)] = v;
        }
    }

    // ---- sparse extras: k != 13 ----
    for (int k = 0; k < 27; k++) {
        if (k == 13) continue;
        __syncthreads();                    // prev-k processing + init done
        if (t == 0) nV = 0;
        const float4* Wk4 = (const float4*)(W + (size_t)k * INC * 32);
        for (int i = t; i < INC * 8; i += 256)
            ((float4*)Ws)[i] = __ldg(Wk4 + i);
        int nb = -1;
        if (myrow < N) nb = __ldg(&nbr[(size_t)myrow * 27 + k]);
        const bool valid = nb >= 0;
        __syncthreads();                    // nV reset + Ws staged
        unsigned m = __ballot_sync(0xffffffffu, valid);
        if (m) {
            int leader = __ffs(m) - 1;
            int wbase = 0;
            if (lane == leader) wbase = atomicAdd(&nV, __popc(m));
            wbase = __shfl_sync(0xffffffffu, wbase, leader);
            if (valid) {
                int pos = wbase + __popc(m & ((1u << lane) - 1));
                ent_r[pos] = t;
                ent_n[pos] = nb;
            }
        }
        __syncthreads();                    // list final
        const int total = nV;
        for (int e = wid; e < total; e += 8) {
            int row = ent_r[e];
            int ni  = ent_n[e];
            const float4* xr = (const float4*)(x + (size_t)ni * ldx);
            float a = 0.f;
#pragma unroll
            for (int u = 0; u < U; u++) {
                float4 xq = __ldg(xr + u);          // warp-broadcast
                a += xq.x * Ws[(4*u+0)*32 + lane]
                   + xq.y * Ws[(4*u+1)*32 + lane]
                   + xq.z * Ws[(4*u+2)*32 + lane]
                   + xq.w * Ws[(4*u+3)*32 + lane];
            }
            accum[row * ACP + lane] += a;           // rows unique within k
        }
    }

    // ---- dense self tap (k = 13), register-tiled ----
    __syncthreads();
    {
        const float4* Wk4 = (const float4*)(W + (size_t)13 * INC * 32);
        for (int i = t; i < INC * 8; i += 256)
            ((float4*)Ws)[i] = __ldg(Wk4 + i);
    }
    __syncthreads();

    const int cg  = t & 3;
    const int rg  = t >> 2;
    const int r0  = rg * 4;
    const int c0  = cg * 8;
    const int key = rg & 7;

    u64 acc[4][4];
#pragma unroll
    for (int rr = 0; rr < 4; rr++)
#pragma unroll
        for (int i = 0; i < 4; i++) acc[rr][i] = 0ull;

#pragma unroll
    for (int j0 = 0; j0 < INC; j0 += 4) {
        const int slot = ((j0 >> 2) ^ key) << 2;
        float4 xv[4];
#pragma unroll
        for (int rr = 0; rr < 4; rr++)
            xv[rr] = *(const float4*)&Xs[(r0 + rr) * INC + slot];
#pragma unroll
        for (int jj = 0; jj < 4; jj++) {
            double2 wa = *(const double2*)&Ws[(j0 + jj) * 32 + c0];
            double2 wb = *(const double2*)&Ws[(j0 + jj) * 32 + c0 + 4];
            u64 w0 = d2u(wa.x), w1 = d2u(wa.y);
            u64 w2_ = d2u(wb.x), w3 = d2u(wb.y);
#pragma unroll
            for (int rr = 0; rr < 4; rr++) {
                float xs_ = (jj == 0) ? xv[rr].x : (jj == 1) ? xv[rr].y
                          : (jj == 2) ? xv[rr].z : xv[rr].w;
                u64 xd = dup2(xs_);
                fma2(acc[rr][0], xd, w0);
                fma2(acc[rr][1], xd, w1);
                fma2(acc[rr][2], xd, w2_);
                fma2(acc[rr][3], xd, w3);
            }
        }
    }

    // ---- merge + LN(32) + ReLU + store ----
    float4 g0 = *(const float4*)&gam[c0], g1 = *(const float4*)&gam[c0 + 4];
    float4 e0 = *(const float4*)&bet[c0], e1 = *(const float4*)&bet[c0 + 4];
#pragma unroll
    for (int rr = 0; rr < 4; rr++) {
        const int row = r0 + rr;
        const float* ap = accum + row * ACP + c0;
        u64 a0 = addp(acc[rr][0], *(const u64*)(ap + 0));
        u64 a1 = addp(acc[rr][1], *(const u64*)(ap + 2));
        u64 a2 = addp(acc[rr][2], *(const u64*)(ap + 4));
        u64 a3 = addp(acc[rr][3], *(const u64*)(ap + 6));
        float2 v0 = up2(a0), v1 = up2(a1), v2 = up2(a2), v3 = up2(a3);
        float s  = v0.x + v0.y + v1.x + v1.y + v2.x + v2.y + v3.x + v3.y;
        float s2 = v0.x*v0.x + v0.y*v0.y + v1.x*v1.x + v1.y*v1.y
                 + v2.x*v2.x + v2.y*v2.y + v3.x*v3.x + v3.y*v3.y;
#pragma unroll
        for (int o = 2; o > 0; o >>= 1) {
            s  += __shfl_xor_sync(0xffffffffu, s,  o);
            s2 += __shfl_xor_sync(0xffffffffu, s2, o);
        }
        float mu  = s * (1.f / 32.f);
        float var = s2 * (1.f / 32.f) - mu * mu;
        float inv = rsqrtf(var + 1e-5f);
        int grow = base + row;
        if (grow < N) {
            float4 o0, o1;
            o0.x = fmaxf((v0.x - mu) * inv * g0.x + e0.x, 0.f);
            o0.y = fmaxf((v0.y - mu) * inv * g0.y + e0.y, 0.f);
            o0.z = fmaxf((v1.x - mu) * inv * g0.z + e0.z, 0.f);
            o0.w = fmaxf((v1.y - mu) * inv * g0.w + e0.w, 0.f);
            o1.x = fmaxf((v2.x - mu) * inv * g1.x + e1.x, 0.f);
            o1.y = fmaxf((v2.y - mu) * inv * g1.y + e1.y, 0.f);
            o1.z = fmaxf((v3.x - mu) * inv * g1.z + e1.z, 0.f);
            o1.w = fmaxf((v3.y - mu) * inv * g1.w + e1.w, 0.f);
            *(float4*)&out[(size_t)grow * ldo + c0]     = o0;
            *(float4*)&out[(size_t)grow * ldo + c0 + 4] = o1;
        }
    }
}

// ---------------------------------------------------------------------------
extern "C" void kernel_launch(void* const* d_in, const int* in_sizes, int n_in,
                              void* d_out, int out_size)
{
    const float* vox = (const float*)d_in[0];
    const int*   nbr = (const int*)d_in[1];
    const float* W1  = (const float*)d_in[2];
    const float* b1  = (const float*)d_in[3];
    const float* g1  = (const float*)d_in[4];
    const float* be1 = (const float*)d_in[5];
    const float* W2  = (const float*)d_in[6];
    const float* b2  = (const float*)d_in[7];
    const float* g2  = (const float*)d_in[8];
    const float* be2 = (const float*)d_in[9];
    const float* W3  = (const float*)d_in[10];
    const float* b3  = (const float*)d_in[11];
    const float* g3  = (const float*)d_in[12];
    const float* be3 = (const float*)d_in[13];
    const float* W4  = (const float*)d_in[14];
    const float* b4  = (const float*)d_in[15];
    const float* g4  = (const float*)d_in[16];
    const float* be4 = (const float*)d_in[17];
    const float* W5  = (const float*)d_in[18];
    const float* b5  = (const float*)d_in[19];
    const float* g5  = (const float*)d_in[20];
    const float* be5 = (const float*)d_in[21];
    const float* W6  = (const float*)d_in[22];
    const float* b6  = (const float*)d_in[23];
    const float* g6  = (const float*)d_in[24];
    const float* be6 = (const float*)d_in[25];
    const float* W7  = (const float*)d_in[26];
    const float* b7  = (const float*)d_in[27];
    const float* g7  = (const float*)d_in[28];
    const float* be7 = (const float*)d_in[29];

    const int N = in_sizes[0] / 64;

    float* cat = nullptr;
    cudaGetSymbolAddress((void**)&cat, g_cat);

    const int nb1 = (N + 127) / 128;
    const int nbc = (N + 255) / 256;

    const int smem_blk1 = (128 * 68 + 64 * 68) * 4;                  // 52,224 B
    const int smem_c64  = (256 * 34 + 64 * 32 + 256 * 64) * 4 + 2048; // 110,592 B
    const int smem_c32  = (256 * 34 + 32 * 32 + 256 * 32) * 4 + 2048; //  73,728 B
    cudaFuncSetAttribute(blk1_kernel<64>,
                         cudaFuncAttributeMaxDynamicSharedMemorySize, smem_blk1);
    cudaFuncSetAttribute(blk1_kernel<256>,
                         cudaFuncAttributeMaxDynamicSharedMemorySize, smem_blk1);
    cudaFuncSetAttribute(conv_kernel<64>,
                         cudaFuncAttributeMaxDynamicSharedMemorySize, smem_c64);
    cudaFuncSetAttribute(conv_kernel<32>,
                         cudaFuncAttributeMaxDynamicSharedMemorySize, smem_c32);

    // f1, f2
    blk1_kernel<64><<<nb1, 256, smem_blk1>>>(vox, 64, W1, b1, g1, be1, cat + 0,  256, N);
    blk1_kernel<64><<<nb1, 256, smem_blk1>>>(vox, 64, W2, b2, g2, be2, cat + 64, 256, N);
    // f3..f6 (sparse submanifold convs, chained)
    conv_kernel<64><<<nbc, 256, smem_c64>>>(cat + 64,  256, nbr, W3, b3, g3, be3, cat + 128, 256, N);
    conv_kernel<32><<<nbc, 256, smem_c32>>>(cat + 128, 256, nbr, W4, b4, g4, be4, cat + 160, 256, N);
    conv_kernel<32><<<nbc, 256, smem_c32>>>(cat + 160, 256, nbr, W5, b5, g5, be5, cat + 192, 256, N);
    conv_kernel<32><<<nbc, 256, smem_c32>>>(cat + 192, 256, nbr, W6, b6, g6, be6, cat + 224, 256, N);
    // final: blk1 over concat(256) -> out(64)
    blk1_kernel<256><<<nb1, 256, smem_blk1>>>(cat, 256, W7, b7, g7, be7,
                                              (float*)d_out, 64, N);
}

// round 7
// speedup vs baseline: 5.5336x; 1.3246x over previous
#include <cuda_runtime.h>

#define MAX_N 262144
__device__ float g_cat[(size_t)MAX_N * 256];

typedef unsigned long long u64;

__device__ __forceinline__ u64 pk2(float a, float b) {
    u64 r;
    asm("mov.b64 %0, {%1, %2};" : "=l"(r)
        : "r"(__float_as_uint(a)), "r"(__float_as_uint(b)));
    return r;
}
__device__ __forceinline__ u64 dup2(float a) {
    u64 r; unsigned ai = __float_as_uint(a);
    asm("mov.b64 %0, {%1, %1};" : "=l"(r) : "r"(ai));
    return r;
}
__device__ __forceinline__ float2 up2(u64 v) {
    unsigned a, b;
    asm("mov.b64 {%0, %1}, %2;" : "=r"(a), "=r"(b) : "l"(v));
    return make_float2(__uint_as_float(a), __uint_as_float(b));
}
__device__ __forceinline__ void fma2(u64& d, u64 a, u64 b) {
    asm("fma.rn.f32x2 %0, %1, %2, %0;" : "+l"(d) : "l"(a), "l"(b));
}
__device__ __forceinline__ u64 addp(u64 a, u64 b) {
    u64 r;
    asm("add.rn.f32x2 %0, %1, %2;" : "=l"(r) : "l"(a), "l"(b));
    return r;
}
__device__ __forceinline__ u64 d2u(double d) { return __double_as_longlong(d); }

// ---------------------------------------------------------------------------
// blk1_dual: f1 = relu(LN(x@W1+b1)), f2 = relu(LN(x@W2+b2)) in one pass.
// 64 rows/block, 256 threads; thread tile 4 rows x 8 ch; half = which W set.
// ---------------------------------------------------------------------------
__global__ __launch_bounds__(256)
void blk1_dual_kernel(const float* __restrict__ x,
                      const float* __restrict__ W1, const float* __restrict__ b1,
                      const float* __restrict__ g1, const float* __restrict__ be1,
                      const float* __restrict__ W2, const float* __restrict__ b2,
                      const float* __restrict__ g2, const float* __restrict__ be2,
                      float* __restrict__ out, int N)
{
    constexpr int ROWS = 64, PX = 68, PW = 68;
    extern __shared__ float sm[];
    float* Xs = sm;                    // [64][PX] swizzled
    float* Ws = sm + ROWS * PX;        // [2][64][PW] quad-permuted

    const int t    = threadIdx.x;
    const int cg   = t & 15;
    const int rg   = t >> 4;           // 0..15
    const int r0   = rg * 4;
    const int half = cg >> 3;
    const int c0   = (cg & 7) * 8;
    const int key  = rg & 7;
    const int base = blockIdx.x * ROWS;

    // stage both W sets quad-permuted
    for (int idx = t; idx < 64 * 16; idx += 256) {
        int j = idx >> 4, q = idx & 15;
        int pq = (q >> 1) + ((q & 1) << 3);
        *(float4*)&Ws[j * PW + pq * 4]            = *(const float4*)&W1[j * 64 + q * 4];
        *(float4*)&Ws[64 * PW + j * PW + pq * 4]  = *(const float4*)&W2[j * 64 + q * 4];
    }
    // stage X swizzled
    for (int idx = t; idx < ROWS * 16; idx += 256) {
        int r = idx >> 4, u = idx & 15;
        int row = base + r;
        float4 v = make_float4(0.f, 0.f, 0.f, 0.f);
        if (row < N) v = *(const float4*)&x[(size_t)row * 64 + u * 4];
        *(float4*)&Xs[r * PX + ((u ^ ((r >> 2) & 7)) << 2)] = v;
    }
    __syncthreads();

    const float* Wh = Ws + half * 64 * PW;
    const float* bb = half ? b2 : b1;
    const float* gg = half ? g2 : g1;
    const float* ee = half ? be2 : be1;

    u64 acc[4][4];
    {
        u64 p0 = pk2(bb[c0 + 0], bb[c0 + 1]);
        u64 p1 = pk2(bb[c0 + 2], bb[c0 + 3]);
        u64 p2 = pk2(bb[c0 + 4], bb[c0 + 5]);
        u64 p3 = pk2(bb[c0 + 6], bb[c0 + 7]);
#pragma unroll
        for (int rr = 0; rr < 4; rr++) {
            acc[rr][0] = p0; acc[rr][1] = p1; acc[rr][2] = p2; acc[rr][3] = p3;
        }
    }

#pragma unroll
    for (int j0 = 0; j0 < 64; j0 += 4) {
        const int slot = ((j0 >> 2) ^ key) << 2;
        float4 xv[4];
#pragma unroll
        for (int rr = 0; rr < 4; rr++)
            xv[rr] = *(const float4*)&Xs[(r0 + rr) * PX + slot];
#pragma unroll
        for (int jj = 0; jj < 4; jj++) {
            double2 wa = *(const double2*)&Wh[(j0 + jj) * PW + ((cg & 7) << 2)];
            double2 wb = *(const double2*)&Wh[(j0 + jj) * PW + 32 + ((cg & 7) << 2)];
            u64 w0 = d2u(wa.x), w1 = d2u(wa.y);
            u64 w2_ = d2u(wb.x), w3 = d2u(wb.y);
#pragma unroll
            for (int rr = 0; rr < 4; rr++) {
                float xs_ = (jj == 0) ? xv[rr].x : (jj == 1) ? xv[rr].y
                          : (jj == 2) ? xv[rr].z : xv[rr].w;
                u64 xd = dup2(xs_);
                fma2(acc[rr][0], xd, w0);
                fma2(acc[rr][1], xd, w1);
                fma2(acc[rr][2], xd, w2_);
                fma2(acc[rr][3], xd, w3);
            }
        }
    }

    // LN over the 64 channels of this half: 8-lane aligned groups
    float4 ga = *(const float4*)&gg[c0], gb = *(const float4*)&gg[c0 + 4];
    float4 ea = *(const float4*)&ee[c0], eb = *(const float4*)&ee[c0 + 4];
#pragma unroll
    for (int rr = 0; rr < 4; rr++) {
        float2 v0 = up2(acc[rr][0]), v1 = up2(acc[rr][1]);
        float2 v2 = up2(acc[rr][2]), v3 = up2(acc[rr][3]);
        float s  = v0.x + v0.y + v1.x + v1.y + v2.x + v2.y + v3.x + v3.y;
        float s2 = v0.x*v0.x + v0.y*v0.y + v1.x*v1.x + v1.y*v1.y
                 + v2.x*v2.x + v2.y*v2.y + v3.x*v3.x + v3.y*v3.y;
#pragma unroll
        for (int o = 4; o > 0; o >>= 1) {
            s  += __shfl_xor_sync(0xffffffffu, s,  o);
            s2 += __shfl_xor_sync(0xffffffffu, s2, o);
        }
        float mu  = s * (1.f / 64.f);
        float var = s2 * (1.f / 64.f) - mu * mu;
        float inv = rsqrtf(var + 1e-5f);
        int row = base + r0 + rr;
        if (row < N) {
            float4 o0, o1;
            o0.x = fmaxf((v0.x - mu) * inv * ga.x + ea.x, 0.f);
            o0.y = fmaxf((v0.y - mu) * inv * ga.y + ea.y, 0.f);
            o0.z = fmaxf((v1.x - mu) * inv * ga.z + ea.z, 0.f);
            o0.w = fmaxf((v1.y - mu) * inv * ga.w + ea.w, 0.f);
            o1.x = fmaxf((v2.x - mu) * inv * gb.x + eb.x, 0.f);
            o1.y = fmaxf((v2.y - mu) * inv * gb.y + eb.y, 0.f);
            o1.z = fmaxf((v3.x - mu) * inv * gb.z + eb.z, 0.f);
            o1.w = fmaxf((v3.y - mu) * inv * gb.w + eb.w, 0.f);
            float* op = &out[(size_t)row * 256 + half * 64 + c0];
            *(float4*)op       = o0;
            *(float4*)(op + 4) = o1;
        }
    }
}

// ---------------------------------------------------------------------------
// blk1 (INC=256 final layer): y = relu(LN(x @ W + b)), outC = 64.
// ---------------------------------------------------------------------------
template <int INC>
__global__ __launch_bounds__(256)
void blk1_kernel(const float* __restrict__ x, int ldx,
                 const float* __restrict__ W,
                 const float* __restrict__ bias,
                 const float* __restrict__ gam,
                 const float* __restrict__ bet,
                 float* __restrict__ out, int ldo, int N)
{
    constexpr int KC = 64;
    constexpr int PX = 68;
    constexpr int PW = 68;
    constexpr int ROWS = 128;
    extern __shared__ float sm[];
    float* Xs = sm;
    float* Ws = sm + ROWS * PX;

    const int t   = threadIdx.x;
    const int cg  = t & 7;
    const int rg  = t >> 3;
    const int r0  = rg * 4;
    const int c0  = cg * 8;
    const int key = rg & 7;
    const int base = blockIdx.x * ROWS;

    u64 acc[4][4];
    {
        u64 b0 = pk2(bias[c0 + 0], bias[c0 + 1]);
        u64 b1 = pk2(bias[c0 + 2], bias[c0 + 3]);
        u64 b2 = pk2(bias[c0 + 4], bias[c0 + 5]);
        u64 b3 = pk2(bias[c0 + 6], bias[c0 + 7]);
#pragma unroll
        for (int rr = 0; rr < 4; rr++) {
            acc[rr][0] = b0; acc[rr][1] = b1; acc[rr][2] = b2; acc[rr][3] = b3;
        }
    }

    for (int k0 = 0; k0 < INC; k0 += KC) {
        __syncthreads();
        for (int idx = t; idx < KC * 16; idx += 256) {
            int j = idx >> 4, q = idx & 15;
            int pq = (q >> 1) + ((q & 1) << 3);
            *(float4*)&Ws[j * PW + pq * 4] =
                *(const float4*)&W[(size_t)(k0 + j) * 64 + q * 4];
        }
        for (int idx = t; idx < ROWS * 16; idx += 256) {
            int r = idx >> 4, u = idx & 15;
            int row = base + r;
            float4 v = make_float4(0.f, 0.f, 0.f, 0.f);
            if (row < N)
                v = *(const float4*)&x[(size_t)row * ldx + k0 + u * 4];
            *(float4*)&Xs[r * PX + ((u ^ ((r >> 2) & 7)) << 2)] = v;
        }
        __syncthreads();

#pragma unroll
        for (int j0 = 0; j0 < KC; j0 += 4) {
            const int slot = ((j0 >> 2) ^ key) << 2;
            float4 xv[4];
#pragma unroll
            for (int rr = 0; rr < 4; rr++)
                xv[rr] = *(const float4*)&Xs[(r0 + rr) * PX + slot];
#pragma unroll
            for (int jj = 0; jj < 4; jj++) {
                double2 wa = *(const double2*)&Ws[(j0 + jj) * PW + (cg << 2)];
                double2 wb = *(const double2*)&Ws[(j0 + jj) * PW + 32 + (cg << 2)];
                u64 w0 = d2u(wa.x), w1 = d2u(wa.y);
                u64 w2_ = d2u(wb.x), w3 = d2u(wb.y);
#pragma unroll
                for (int rr = 0; rr < 4; rr++) {
                    float xs_ = (jj == 0) ? xv[rr].x : (jj == 1) ? xv[rr].y
                              : (jj == 2) ? xv[rr].z : xv[rr].w;
                    u64 xd = dup2(xs_);
                    fma2(acc[rr][0], xd, w0);
                    fma2(acc[rr][1], xd, w1);
                    fma2(acc[rr][2], xd, w2_);
                    fma2(acc[rr][3], xd, w3);
                }
            }
        }
    }

    float4 g0 = *(const float4*)&gam[c0], g1 = *(const float4*)&gam[c0 + 4];
    float4 e0 = *(const float4*)&bet[c0], e1 = *(const float4*)&bet[c0 + 4];
#pragma unroll
    for (int rr = 0; rr < 4; rr++) {
        float2 v0 = up2(acc[rr][0]), v1 = up2(acc[rr][1]);
        float2 v2 = up2(acc[rr][2]), v3 = up2(acc[rr][3]);
        float s  = v0.x + v0.y + v1.x + v1.y + v2.x + v2.y + v3.x + v3.y;
        float s2 = v0.x*v0.x + v0.y*v0.y + v1.x*v1.x + v1.y*v1.y
                 + v2.x*v2.x + v2.y*v2.y + v3.x*v3.x + v3.y*v3.y;
#pragma unroll
        for (int o = 4; o > 0; o >>= 1) {
            s  += __shfl_xor_sync(0xffffffffu, s,  o);
            s2 += __shfl_xor_sync(0xffffffffu, s2, o);
        }
        float mu  = s * (1.f / 64.f);
        float var = s2 * (1.f / 64.f) - mu * mu;
        float inv = rsqrtf(var + 1e-5f);
        int row = base + r0 + rr;
        if (row < N) {
            float4 o0, o1;
            o0.x = fmaxf((v0.x - mu) * inv * g0.x + e0.x, 0.f);
            o0.y = fmaxf((v0.y - mu) * inv * g0.y + e0.y, 0.f);
            o0.z = fmaxf((v1.x - mu) * inv * g0.z + e0.z, 0.f);
            o0.w = fmaxf((v1.y - mu) * inv * g0.w + e0.w, 0.f);
            o1.x = fmaxf((v2.x - mu) * inv * g1.x + e1.x, 0.f);
            o1.y = fmaxf((v2.y - mu) * inv * g1.y + e1.y, 0.f);
            o1.z = fmaxf((v3.x - mu) * inv * g1.z + e1.z, 0.f);
            o1.w = fmaxf((v3.y - mu) * inv * g1.w + e1.w, 0.f);
            *(float4*)&out[(size_t)row * ldo + c0]     = o0;
            *(float4*)&out[(size_t)row * ldo + c0 + 4] = o1;
        }
    }
}

// ---------------------------------------------------------------------------
// Sparse submanifold conv, single-pass. 128 rows/block, 256 threads.
// Warps 0-3: build one (k,row,nbr) entry list for all 26 non-self taps.
// Warps 4-7: zero accum, stage Xs (swizzled) and the self-tap W.
// Then all warps: warp-per-entry sparse accumulation (W straight from gmem,
// coalesced; x row broadcast; smem atomicAdd), dense self tap in registers,
// merge + LN(32) + ReLU.
// ACP = 36 floats (144 B) so every accum row is 16B-aligned for float4 ops.
// ---------------------------------------------------------------------------
template <int INC>
__global__ __launch_bounds__(256)
void conv_kernel(const float* __restrict__ x, int ldx,
                 const int* __restrict__ nbr,      // [N][27]
                 const float* __restrict__ W,      // [27][INC][32]
                 const float* __restrict__ bias,
                 const float* __restrict__ gam,
                 const float* __restrict__ bet,
                 float* __restrict__ out, int ldo, int N)
{
    constexpr int ROWS = 128;
    constexpr int ACP  = 36;       // 144 B row pitch: 16B-aligned, 4-bank offset
    constexpr int U    = INC / 4;
    constexpr int MAXE = ROWS * 26;
    extern __shared__ float sm[];
    float* accum = sm;                         // [128][ACP]
    float* Xs    = accum + ROWS * ACP;         // [128][INC] swizzled
    float* Ws    = Xs + ROWS * INC;            // [INC][32] self-tap W
    int*   ent_a = (int*)(Ws + INC * 32);      // [MAXE] (k<<7)|row
    int*   ent_n = ent_a + MAXE;               // [MAXE]
    __shared__ int nV;

    const int t    = threadIdx.x;
    const int lane = t & 31;
    const int wid  = t >> 5;
    const int base = blockIdx.x * ROWS;

    if (t == 0) nV = 0;
    __syncthreads();

    if (t < ROWS) {
        // ---- list builders (warps 0-3) ----
        const int myrow = base + t;
        int nb[27];
#pragma unroll
        for (int k = 0; k < 27; k++)
            nb[k] = (myrow < N) ? __ldg(&nbr[(size_t)myrow * 27 + k]) : -1;
#pragma unroll
        for (int k = 0; k < 27; k++) {
            if (k == 13) continue;
            const bool valid = nb[k] >= 0;
            unsigned m = __ballot_sync(0xffffffffu, valid);
            if (m) {
                int leader = __ffs(m) - 1;
                int wbase = 0;
                if (lane == leader) wbase = atomicAdd(&nV, __popc(m));
                wbase = __shfl_sync(0xffffffffu, wbase, leader);
                if (valid) {
                    int pos = wbase + __popc(m & ((1u << lane) - 1));
                    ent_a[pos] = (k << 7) | t;
                    ent_n[pos] = nb[k];
                }
            }
        }
    } else {
        // ---- stagers (warps 4-7) ----
        const int r = t - ROWS;                 // 0..127
        float* ar = accum + r * ACP;            // 16B-aligned (ACP=36)
#pragma unroll
        for (int c = 0; c < 8; c++) ((float4*)ar)[c] = make_float4(0.f, 0.f, 0.f, 0.f);
        const int row = base + r;
        const int skey = (r >> 1) & 7;
        const float4* xr = (const float4*)(x + (size_t)row * ldx);
#pragma unroll
        for (int u = 0; u < U; u++) {
            float4 v = make_float4(0.f, 0.f, 0.f, 0.f);
            if (row < N) v = __ldg(xr + u);
            *(float4*)&Xs[r * INC + ((u ^ skey) << 2)] = v;
        }
        const float4* Wk4 = (const float4*)(W + (size_t)13 * INC * 32);
        for (int i = r; i < INC * 8; i += 128)
            ((float4*)Ws)[i] = __ldg(Wk4 + i);
    }
    __syncthreads();

    // ---- sparse phase: warp per entry ----
    const int total = nV;
    for (int e = wid; e < total; e += 8) {
        int a   = ent_a[e];
        int row = a & 127;
        int k   = a >> 7;
        int ni  = ent_n[e];
        const float4* xr = (const float4*)(x + (size_t)ni * ldx);
        const float*  Wk = W + (size_t)k * INC * 32 + lane;
        float acc_ = 0.f;
#pragma unroll
        for (int u = 0; u < U; u++) {
            float4 xq = __ldg(xr + u);              // warp broadcast
            const float* Wj = Wk + u * 128;
            acc_ += xq.x * __ldg(Wj)
                  + xq.y * __ldg(Wj + 32)
                  + xq.z * __ldg(Wj + 64)
                  + xq.w * __ldg(Wj + 96);
        }
        atomicAdd(&accum[row * ACP + lane], acc_);
    }
    __syncthreads();

    // ---- dense self tap (k=13), register tiled: 2 rows x 8 ch ----
    const int cg  = t & 3;
    const int rg  = t >> 2;                  // 0..63
    const int r0  = rg * 2;
    const int c0  = cg * 8;
    const int key = rg & 7;

    u64 acc[2][4];
    {
        u64 b0 = pk2(bias[c0 + 0], bias[c0 + 1]);
        u64 b1 = pk2(bias[c0 + 2], bias[c0 + 3]);
        u64 b2 = pk2(bias[c0 + 4], bias[c0 + 5]);
        u64 b3 = pk2(bias[c0 + 6], bias[c0 + 7]);
#pragma unroll
        for (int rr = 0; rr < 2; rr++) {
            acc[rr][0] = b0; acc[rr][1] = b1; acc[rr][2] = b2; acc[rr][3] = b3;
        }
    }

#pragma unroll
    for (int j0 = 0; j0 < INC; j0 += 4) {
        const int slot = ((j0 >> 2) ^ key) << 2;
        float4 xv[2];
#pragma unroll
        for (int rr = 0; rr < 2; rr++)
            xv[rr] = *(const float4*)&Xs[(r0 + rr) * INC + slot];
#pragma unroll
        for (int jj = 0; jj < 4; jj++) {
            double2 wa = *(const double2*)&Ws[(j0 + jj) * 32 + c0];
            double2 wb = *(const double2*)&Ws[(j0 + jj) * 32 + c0 + 4];
            u64 w0 = d2u(wa.x), w1 = d2u(wa.y);
            u64 w2_ = d2u(wb.x), w3 = d2u(wb.y);
#pragma unroll
            for (int rr = 0; rr < 2; rr++) {
                float xs_ = (jj == 0) ? xv[rr].x : (jj == 1) ? xv[rr].y
                          : (jj == 2) ? xv[rr].z : xv[rr].w;
                u64 xd = dup2(xs_);
                fma2(acc[rr][0], xd, w0);
                fma2(acc[rr][1], xd, w1);
                fma2(acc[rr][2], xd, w2_);
                fma2(acc[rr][3], xd, w3);
            }
        }
    }

    // ---- merge + LN(32) + ReLU + store ----
    float4 g0 = *(const float4*)&gam[c0], g1 = *(const float4*)&gam[c0 + 4];
    float4 e0 = *(const float4*)&bet[c0], e1 = *(const float4*)&bet[c0 + 4];
#pragma unroll
    for (int rr = 0; rr < 2; rr++) {
        const int row = r0 + rr;
        const float* ap = accum + row * ACP + c0;
        u64 a0 = addp(acc[rr][0], *(const u64*)(ap + 0));
        u64 a1 = addp(acc[rr][1], *(const u64*)(ap + 2));
        u64 a2 = addp(acc[rr][2], *(const u64*)(ap + 4));
        u64 a3 = addp(acc[rr][3], *(const u64*)(ap + 6));
        float2 v0 = up2(a0), v1 = up2(a1), v2 = up2(a2), v3 = up2(a3);
        float s  = v0.x + v0.y + v1.x + v1.y + v2.x + v2.y + v3.x + v3.y;
        float s2 = v0.x*v0.x + v0.y*v0.y + v1.x*v1.x + v1.y*v1.y
                 + v2.x*v2.x + v2.y*v2.y + v3.x*v3.x + v3.y*v3.y;
#pragma unroll
        for (int o = 2; o > 0; o >>= 1) {
            s  += __shfl_xor_sync(0xffffffffu, s,  o);
            s2 += __shfl_xor_sync(0xffffffffu, s2, o);
        }
        float mu  = s * (1.f / 32.f);
        float var = s2 * (1.f / 32.f) - mu * mu;
        float inv = rsqrtf(var + 1e-5f);
        int grow = base + row;
        if (grow < N) {
            float4 o0, o1;
            o0.x = fmaxf((v0.x - mu) * inv * g0.x + e0.x, 0.f);
            o0.y = fmaxf((v0.y - mu) * inv * g0.y + e0.y, 0.f);
            o0.z = fmaxf((v1.x - mu) * inv * g0.z + e0.z, 0.f);
            o0.w = fmaxf((v1.y - mu) * inv * g0.w + e0.w, 0.f);
            o1.x = fmaxf((v2.x - mu) * inv * g1.x + e1.x, 0.f);
            o1.y = fmaxf((v2.y - mu) * inv * g1.y + e1.y, 0.f);
            o1.z = fmaxf((v3.x - mu) * inv * g1.z + e1.z, 0.f);
            o1.w = fmaxf((v3.y - mu) * inv * g1.w + e1.w, 0.f);
            *(float4*)&out[(size_t)grow * ldo + c0]     = o0;
            *(float4*)&out[(size_t)grow * ldo + c0 + 4] = o1;
        }
    }
}

// ---------------------------------------------------------------------------
extern "C" void kernel_launch(void* const* d_in, const int* in_sizes, int n_in,
                              void* d_out, int out_size)
{
    const float* vox = (const float*)d_in[0];
    const int*   nbr = (const int*)d_in[1];
    const float* W1  = (const float*)d_in[2];
    const float* b1  = (const float*)d_in[3];
    const float* g1  = (const float*)d_in[4];
    const float* be1 = (const float*)d_in[5];
    const float* W2  = (const float*)d_in[6];
    const float* b2  = (const float*)d_in[7];
    const float* g2  = (const float*)d_in[8];
    const float* be2 = (const float*)d_in[9];
    const float* W3  = (const float*)d_in[10];
    const float* b3  = (const float*)d_in[11];
    const float* g3  = (const float*)d_in[12];
    const float* be3 = (const float*)d_in[13];
    const float* W4  = (const float*)d_in[14];
    const float* b4  = (const float*)d_in[15];
    const float* g4  = (const float*)d_in[16];
    const float* be4 = (const float*)d_in[17];
    const float* W5  = (const float*)d_in[18];
    const float* b5  = (const float*)d_in[19];
    const float* g5  = (const float*)d_in[20];
    const float* be5 = (const float*)d_in[21];
    const float* W6  = (const float*)d_in[22];
    const float* b6  = (const float*)d_in[23];
    const float* g6  = (const float*)d_in[24];
    const float* be6 = (const float*)d_in[25];
    const float* W7  = (const float*)d_in[26];
    const float* b7  = (const float*)d_in[27];
    const float* g7  = (const float*)d_in[28];
    const float* be7 = (const float*)d_in[29];

    const int N = in_sizes[0] / 64;

    float* cat = nullptr;
    cudaGetSymbolAddress((void**)&cat, g_cat);

    const int nbd  = (N + 63) / 64;
    const int nbc  = (N + 127) / 128;
    const int nbf  = (N + 127) / 128;

    const int smem_dual = (64 * 68 + 2 * 64 * 68) * 4;                        // 52,224
    const int smem_f    = (128 * 68 + 64 * 68) * 4;                           // 52,224
    const int smem_c64  = (128 * 36 + 128 * 64 + 64 * 32) * 4 + 128 * 26 * 8; // 86,016
    const int smem_c32  = (128 * 36 + 128 * 32 + 32 * 32) * 4 + 128 * 26 * 8; // 65,536
    cudaFuncSetAttribute(blk1_dual_kernel,
                         cudaFuncAttributeMaxDynamicSharedMemorySize, smem_dual);
    cudaFuncSetAttribute(blk1_kernel<256>,
                         cudaFuncAttributeMaxDynamicSharedMemorySize, smem_f);
    cudaFuncSetAttribute(conv_kernel<64>,
                         cudaFuncAttributeMaxDynamicSharedMemorySize, smem_c64);
    cudaFuncSetAttribute(conv_kernel<32>,
                         cudaFuncAttributeMaxDynamicSharedMemorySize, smem_c32);

    // f1 | f2 fused
    blk1_dual_kernel<<<nbd, 256, smem_dual>>>(vox, W1, b1, g1, be1,
                                              W2, b2, g2, be2, cat, N);
    // f3..f6 (sparse submanifold convs, chained)
    conv_kernel<64><<<nbc, 256, smem_c64>>>(cat + 64,  256, nbr, W3, b3, g3, be3, cat + 128, 256, N);
    conv_kernel<32><<<nbc, 256, smem_c32>>>(cat + 128, 256, nbr, W4, b4, g4, be4, cat + 160, 256, N);
    conv_kernel<32><<<nbc, 256, smem_c32>>>(cat + 160, 256, nbr, W5, b5, g5, be5, cat + 192, 256, N);
    conv_kernel<32><<<nbc, 256, smem_c32>>>(cat + 192, 256, nbr, W6, b6, g6, be6, cat + 224, 256, N);
    // final: blk1 over concat(256) -> out(64)
    blk1_kernel<256><<<nbf, 256, smem_f>>>(cat, 256, W7, b7, g7, be7,
                                           (float*)d_out, 64, N);
}